// round 16
// baseline (speedup 1.0000x reference)
#include <cuda_runtime.h>

// Problem dims: [B=4, C=1, D=64, H=192, W=192], float32
#define BSZ 4
#define DSZ 64
#define HSZ 192
#define WSZ 192
#define HW  (HSZ * WSZ)                 // 36864
#define NVOX (BSZ * DSZ * HSZ * WSZ)    // 9437184
#define NCH 5

// Gaussian 1D weights (sigma=1.5, K=11), normalized. Hardcoded literals so the
// inner-loop FMAs compile to FFMA-immediate (rt_SMSP=1 on sm_103a).
#define GW_INIT { 0.00102838f, 0.00759876f, 0.03600077f, 0.10936070f, \
                  0.21300554f, 0.26601170f, 0.21300554f, 0.10936070f, \
                  0.03600077f, 0.00759876f, 0.00102838f }

#define C1V 1.0e-4f
#define C2V 9.0e-4f

// Scratch (static device globals: allocation-free per harness rules).
// Layout: channel-major, ch in {mu_p_src, mu_t_src, p2, t2, pt} after each pass.
__device__ float g_bufA[(size_t)NCH * NVOX];
__device__ float g_bufB[(size_t)NCH * NVOX];
__device__ double g_accum;

// ---------------------------------------------------------------------------
// Pass 1: W-direction conv, fused channel expansion.
// One block per row (B*D*H = 49152 rows), 192 threads (one per w output).
// Reads pred/target once, writes 5 channels to g_bufA.
// ---------------------------------------------------------------------------
__global__ void __launch_bounds__(WSZ) k_wconv(const float* __restrict__ pred,
                                               const float* __restrict__ targ) {
    if (blockIdx.x == 0 && threadIdx.x == 0) g_accum = 0.0;  // reset reduction (graph-replay safe)

    __shared__ float sp[WSZ + 12];
    __shared__ float st[WSZ + 12];

    const int w = threadIdx.x;
    const size_t base = (size_t)blockIdx.x * WSZ;

    sp[5 + w] = pred[base + w];
    st[5 + w] = targ[base + w];
    if (w < 5) {
        sp[w] = 0.f; st[w] = 0.f;
        sp[WSZ + 5 + w] = 0.f; st[WSZ + 5 + w] = 0.f;
    }
    __syncthreads();

    const float GW[11] = GW_INIT;
    float ap = 0.f, at = 0.f, app = 0.f, att = 0.f, apt = 0.f;
#pragma unroll
    for (int k = 0; k < 11; k++) {
        const float p = sp[w + k];
        const float t = st[w + k];
        const float gp = GW[k] * p;
        const float gt = GW[k] * t;
        ap += gp;
        at += gt;
        app = fmaf(gp, p, app);
        att = fmaf(gt, t, att);
        apt = fmaf(gp, t, apt);
    }

    const size_t o = base + w;
    g_bufA[o]                      = ap;
    g_bufA[(size_t)NVOX * 1 + o]   = at;
    g_bufA[(size_t)NVOX * 2 + o]   = app;
    g_bufA[(size_t)NVOX * 3 + o]   = att;
    g_bufA[(size_t)NVOX * 4 + o]   = apt;
}

// ---------------------------------------------------------------------------
// Pass 2: H-direction conv, register ring-buffer sliding along h.
// One thread per (channel, b, d, w) column: 5*4*64*192 = 245760 threads.
// Each input element is read exactly once; loads/stores coalesced along w.
// ---------------------------------------------------------------------------
__global__ void __launch_bounds__(256) k_hconv() {
    const int tid = blockIdx.x * 256 + threadIdx.x;
    if (tid >= NCH * BSZ * DSZ * WSZ) return;

    const int w    = tid % WSZ;
    const int bd_c = tid / WSZ;
    const int bd   = bd_c % (BSZ * DSZ);
    const int c    = bd_c / (BSZ * DSZ);

    const float* __restrict__ in  = g_bufA + (size_t)c * NVOX + (size_t)bd * HW + w;
    float* __restrict__       out = g_bufB + (size_t)c * NVOX + (size_t)bd * HW + w;

    const float GW[11] = GW_INIT;

    float r[11];
#pragma unroll
    for (int j = 0; j < 5; j++) r[j] = 0.f;
#pragma unroll
    for (int j = 5; j < 11; j++) r[j] = in[(size_t)(j - 5) * WSZ];

#pragma unroll 4
    for (int h = 0; h < HSZ; h++) {
        float acc = 0.f;
#pragma unroll
        for (int k = 0; k < 11; k++) acc = fmaf(GW[k], r[k], acc);
        out[(size_t)h * WSZ] = acc;

#pragma unroll
        for (int k = 0; k < 10; k++) r[k] = r[k + 1];
        const int hn = h + 6;
        r[10] = (hn < HSZ) ? in[(size_t)hn * WSZ] : 0.f;
    }
}

// ---------------------------------------------------------------------------
// Pass 3: D-direction conv (all 5 channels per thread) + SSIM map + reduction.
// One thread per (b, h, w) column: 4*192*192 = 147456 threads, 64 d-steps each.
// ---------------------------------------------------------------------------
__global__ void __launch_bounds__(256) k_dconv_ssim() {
    const int tid = blockIdx.x * 256 + threadIdx.x;

    float lsum = 0.f;
    if (tid < BSZ * HSZ * WSZ) {
        const int w  = tid % WSZ;
        const int hb = tid / WSZ;
        const int h  = hb % HSZ;
        const int b  = hb / HSZ;

        const size_t col = ((size_t)b * DSZ * HSZ + h) * WSZ + w;  // d = 0 element
        const float* __restrict__ p0 = g_bufB + col;
        const float* __restrict__ p1 = p0 + (size_t)NVOX * 1;
        const float* __restrict__ p2 = p0 + (size_t)NVOX * 2;
        const float* __restrict__ p3 = p0 + (size_t)NVOX * 3;
        const float* __restrict__ p4 = p0 + (size_t)NVOX * 4;

        const float GW[11] = GW_INIT;

        float r0[11], r1[11], r2[11], r3[11], r4[11];
#pragma unroll
        for (int j = 0; j < 5; j++) {
            r0[j] = 0.f; r1[j] = 0.f; r2[j] = 0.f; r3[j] = 0.f; r4[j] = 0.f;
        }
#pragma unroll
        for (int j = 5; j < 11; j++) {
            const size_t off = (size_t)(j - 5) * HW;
            r0[j] = p0[off]; r1[j] = p1[off]; r2[j] = p2[off];
            r3[j] = p3[off]; r4[j] = p4[off];
        }

#pragma unroll 2
        for (int d = 0; d < DSZ; d++) {
            float cp = 0.f, ct = 0.f, cpp = 0.f, ctt = 0.f, cpt = 0.f;
#pragma unroll
            for (int k = 0; k < 11; k++) {
                cp  = fmaf(GW[k], r0[k], cp);
                ct  = fmaf(GW[k], r1[k], ct);
                cpp = fmaf(GW[k], r2[k], cpp);
                ctt = fmaf(GW[k], r3[k], ctt);
                cpt = fmaf(GW[k], r4[k], cpt);
            }

            // SSIM at this voxel
            const float mup2 = cp * cp;
            const float mut2 = ct * ct;
            const float mupt = cp * ct;
            const float sig_p = cpp - mup2;
            const float sig_t = ctt - mut2;
            const float sig_pt = cpt - mupt;
            const float num = (2.0f * mupt + C1V) * (2.0f * sig_pt + C2V);
            const float den = (mup2 + mut2 + C1V) * (sig_p + sig_t + C2V);
            lsum += num / den;

            // advance ring
#pragma unroll
            for (int k = 0; k < 10; k++) {
                r0[k] = r0[k + 1]; r1[k] = r1[k + 1]; r2[k] = r2[k + 1];
                r3[k] = r3[k + 1]; r4[k] = r4[k + 1];
            }
            const int dn = d + 6;
            if (dn < DSZ) {
                const size_t off = (size_t)dn * HW;
                r0[10] = p0[off]; r1[10] = p1[off]; r2[10] = p2[off];
                r3[10] = p3[off]; r4[10] = p4[off];
            } else {
                r0[10] = 0.f; r1[10] = 0.f; r2[10] = 0.f; r3[10] = 0.f; r4[10] = 0.f;
            }
        }
    }

    // block reduction (float partials are small: <= 256*64 terms, |term| ~ 0.2)
    __shared__ float sred[256];
    sred[threadIdx.x] = lsum;
    __syncthreads();
#pragma unroll
    for (int s = 128; s > 0; s >>= 1) {
        if (threadIdx.x < s) sred[threadIdx.x] += sred[threadIdx.x + s];
        __syncthreads();
    }
    if (threadIdx.x == 0) atomicAdd(&g_accum, (double)sred[0]);
}

// ---------------------------------------------------------------------------
// Finalize: out = 1 - mean(ssim_map)
// ---------------------------------------------------------------------------
__global__ void k_final(float* __restrict__ out) {
    out[0] = (float)(1.0 - g_accum / (double)NVOX);
}

extern "C" void kernel_launch(void* const* d_in, const int* in_sizes, int n_in,
                              void* d_out, int out_size) {
    const float* pred = (const float*)d_in[0];
    const float* targ = (const float*)d_in[1];
    float* out = (float*)d_out;

    // Pass 1: W conv + channel expansion (also resets the accumulator)
    k_wconv<<<BSZ * DSZ * HSZ, WSZ>>>(pred, targ);

    // Pass 2: H conv over 5 channels
    k_hconv<<<(NCH * BSZ * DSZ * WSZ) / 256, 256>>>();

    // Pass 3: D conv + SSIM + reduction
    k_dconv_ssim<<<(BSZ * HSZ * WSZ) / 256, 256>>>();

    // Finalize scalar
    k_final<<<1, 1>>>(out);
}

// round 17
// speedup vs baseline: 1.0031x; 1.0031x over previous
#include <cuda_runtime.h>

// Problem dims: [B=4, C=1, D=64, H=192, W=192], float32
#define BSZ 4
#define DSZ 64
#define HSZ 192
#define WSZ 192
#define HW  (HSZ * WSZ)                 // 36864
#define NVOX (BSZ * DSZ * HSZ * WSZ)    // 9437184
#define NCH 5

// Gaussian 1D weights (sigma=1.5, K=11), normalized. Hardcoded literals so the
// inner-loop FMAs compile to FFMA-immediate (rt_SMSP=1 on sm_103a).
#define GW_INIT { 0.00102838f, 0.00759876f, 0.03600077f, 0.10936070f, \
                  0.21300554f, 0.26601170f, 0.21300554f, 0.10936070f, \
                  0.03600077f, 0.00759876f, 0.00102838f }

#define C1V 1.0e-4f
#define C2V 9.0e-4f

// Scratch (static device globals: allocation-free per harness rules).
// Layout: channel-major, ch in {mu_p_src, mu_t_src, p2, t2, pt} after each pass.
__device__ float g_bufA[(size_t)NCH * NVOX];
__device__ float g_bufB[(size_t)NCH * NVOX];
__device__ double g_accum;

// ---------------------------------------------------------------------------
// Pass 1: W-direction conv, fused channel expansion.
// One block per row (B*D*H = 49152 rows), 192 threads (one per w output).
// Reads pred/target once, writes 5 channels to g_bufA.
// ---------------------------------------------------------------------------
__global__ void __launch_bounds__(WSZ) k_wconv(const float* __restrict__ pred,
                                               const float* __restrict__ targ) {
    if (blockIdx.x == 0 && threadIdx.x == 0) g_accum = 0.0;  // reset reduction (graph-replay safe)

    __shared__ float sp[WSZ + 12];
    __shared__ float st[WSZ + 12];

    const int w = threadIdx.x;
    const size_t base = (size_t)blockIdx.x * WSZ;

    sp[5 + w] = pred[base + w];
    st[5 + w] = targ[base + w];
    if (w < 5) {
        sp[w] = 0.f; st[w] = 0.f;
        sp[WSZ + 5 + w] = 0.f; st[WSZ + 5 + w] = 0.f;
    }
    __syncthreads();

    const float GW[11] = GW_INIT;
    float ap = 0.f, at = 0.f, app = 0.f, att = 0.f, apt = 0.f;
#pragma unroll
    for (int k = 0; k < 11; k++) {
        const float p = sp[w + k];
        const float t = st[w + k];
        const float gp = GW[k] * p;
        const float gt = GW[k] * t;
        ap += gp;
        at += gt;
        app = fmaf(gp, p, app);
        att = fmaf(gt, t, att);
        apt = fmaf(gp, t, apt);
    }

    const size_t o = base + w;
    g_bufA[o]                      = ap;
    g_bufA[(size_t)NVOX * 1 + o]   = at;
    g_bufA[(size_t)NVOX * 2 + o]   = app;
    g_bufA[(size_t)NVOX * 3 + o]   = att;
    g_bufA[(size_t)NVOX * 4 + o]   = apt;
}

// ---------------------------------------------------------------------------
// Pass 2: H-direction conv, register ring-buffer sliding along h.
// One thread per (channel, b, d, w) column: 5*4*64*192 = 245760 threads.
// Each input element is read exactly once; loads/stores coalesced along w.
// ---------------------------------------------------------------------------
__global__ void __launch_bounds__(256) k_hconv() {
    const int tid = blockIdx.x * 256 + threadIdx.x;
    if (tid >= NCH * BSZ * DSZ * WSZ) return;

    const int w    = tid % WSZ;
    const int bd_c = tid / WSZ;
    const int bd   = bd_c % (BSZ * DSZ);
    const int c    = bd_c / (BSZ * DSZ);

    const float* __restrict__ in  = g_bufA + (size_t)c * NVOX + (size_t)bd * HW + w;
    float* __restrict__       out = g_bufB + (size_t)c * NVOX + (size_t)bd * HW + w;

    const float GW[11] = GW_INIT;

    float r[11];
#pragma unroll
    for (int j = 0; j < 5; j++) r[j] = 0.f;
#pragma unroll
    for (int j = 5; j < 11; j++) r[j] = in[(size_t)(j - 5) * WSZ];

#pragma unroll 4
    for (int h = 0; h < HSZ; h++) {
        float acc = 0.f;
#pragma unroll
        for (int k = 0; k < 11; k++) acc = fmaf(GW[k], r[k], acc);
        out[(size_t)h * WSZ] = acc;

#pragma unroll
        for (int k = 0; k < 10; k++) r[k] = r[k + 1];
        const int hn = h + 6;
        r[10] = (hn < HSZ) ? in[(size_t)hn * WSZ] : 0.f;
    }
}

// ---------------------------------------------------------------------------
// Pass 3: D-direction conv (all 5 channels per thread) + SSIM map + reduction.
// One thread per (b, h, w) column: 4*192*192 = 147456 threads, 64 d-steps each.
// ---------------------------------------------------------------------------
__global__ void __launch_bounds__(256) k_dconv_ssim() {
    const int tid = blockIdx.x * 256 + threadIdx.x;

    float lsum = 0.f;
    if (tid < BSZ * HSZ * WSZ) {
        const int w  = tid % WSZ;
        const int hb = tid / WSZ;
        const int h  = hb % HSZ;
        const int b  = hb / HSZ;

        const size_t col = ((size_t)b * DSZ * HSZ + h) * WSZ + w;  // d = 0 element
        const float* __restrict__ p0 = g_bufB + col;
        const float* __restrict__ p1 = p0 + (size_t)NVOX * 1;
        const float* __restrict__ p2 = p0 + (size_t)NVOX * 2;
        const float* __restrict__ p3 = p0 + (size_t)NVOX * 3;
        const float* __restrict__ p4 = p0 + (size_t)NVOX * 4;

        const float GW[11] = GW_INIT;

        float r0[11], r1[11], r2[11], r3[11], r4[11];
#pragma unroll
        for (int j = 0; j < 5; j++) {
            r0[j] = 0.f; r1[j] = 0.f; r2[j] = 0.f; r3[j] = 0.f; r4[j] = 0.f;
        }
#pragma unroll
        for (int j = 5; j < 11; j++) {
            const size_t off = (size_t)(j - 5) * HW;
            r0[j] = p0[off]; r1[j] = p1[off]; r2[j] = p2[off];
            r3[j] = p3[off]; r4[j] = p4[off];
        }

#pragma unroll 2
        for (int d = 0; d < DSZ; d++) {
            float cp = 0.f, ct = 0.f, cpp = 0.f, ctt = 0.f, cpt = 0.f;
#pragma unroll
            for (int k = 0; k < 11; k++) {
                cp  = fmaf(GW[k], r0[k], cp);
                ct  = fmaf(GW[k], r1[k], ct);
                cpp = fmaf(GW[k], r2[k], cpp);
                ctt = fmaf(GW[k], r3[k], ctt);
                cpt = fmaf(GW[k], r4[k], cpt);
            }

            // SSIM at this voxel
            const float mup2 = cp * cp;
            const float mut2 = ct * ct;
            const float mupt = cp * ct;
            const float sig_p = cpp - mup2;
            const float sig_t = ctt - mut2;
            const float sig_pt = cpt - mupt;
            const float num = (2.0f * mupt + C1V) * (2.0f * sig_pt + C2V);
            const float den = (mup2 + mut2 + C1V) * (sig_p + sig_t + C2V);
            lsum += num / den;

            // advance ring
#pragma unroll
            for (int k = 0; k < 10; k++) {
                r0[k] = r0[k + 1]; r1[k] = r1[k + 1]; r2[k] = r2[k + 1];
                r3[k] = r3[k + 1]; r4[k] = r4[k + 1];
            }
            const int dn = d + 6;
            if (dn < DSZ) {
                const size_t off = (size_t)dn * HW;
                r0[10] = p0[off]; r1[10] = p1[off]; r2[10] = p2[off];
                r3[10] = p3[off]; r4[10] = p4[off];
            } else {
                r0[10] = 0.f; r1[10] = 0.f; r2[10] = 0.f; r3[10] = 0.f; r4[10] = 0.f;
            }
        }
    }

    // block reduction (float partials are small: <= 256*64 terms, |term| ~ 0.2)
    __shared__ float sred[256];
    sred[threadIdx.x] = lsum;
    __syncthreads();
#pragma unroll
    for (int s = 128; s > 0; s >>= 1) {
        if (threadIdx.x < s) sred[threadIdx.x] += sred[threadIdx.x + s];
        __syncthreads();
    }
    if (threadIdx.x == 0) atomicAdd(&g_accum, (double)sred[0]);
}

// ---------------------------------------------------------------------------
// Finalize: out = 1 - mean(ssim_map)
// ---------------------------------------------------------------------------
__global__ void k_final(float* __restrict__ out) {
    out[0] = (float)(1.0 - g_accum / (double)NVOX);
}

extern "C" void kernel_launch(void* const* d_in, const int* in_sizes, int n_in,
                              void* d_out, int out_size) {
    const float* pred = (const float*)d_in[0];
    const float* targ = (const float*)d_in[1];
    float* out = (float*)d_out;

    // Pass 1: W conv + channel expansion (also resets the accumulator)
    k_wconv<<<BSZ * DSZ * HSZ, WSZ>>>(pred, targ);

    // Pass 2: H conv over 5 channels
    k_hconv<<<(NCH * BSZ * DSZ * WSZ) / 256, 256>>>();

    // Pass 3: D conv + SSIM + reduction
    k_dconv_ssim<<<(BSZ * HSZ * WSZ) / 256, 256>>>();

    // Finalize scalar
    k_final<<<1, 1>>>(out);
}